// round 5
// baseline (speedup 1.0000x reference)
#include <cuda_runtime.h>
#include <cuda_bf16.h>
#include <cstdint>

// ============================================================================
// softassignment on B200 (sm_100a), round 5 (= round-4 source; round-4 bench
// died to an infra container failure before any HW evidence was produced).
//   out = intranorm( softmax(alpha*<x_b, zhat_bk>) @ zhat_b ), exact identities:
//   - softmax(-a(1-dot)) == softmax(a*dot)
//   - softmax denominator cancels in final per-book L2 norm (never computed)
//   - row-max replaced by Cauchy-Schwarz bound M = a*L2E*||x_b|| - 50
// Precision: 3-term split-bf16 MMAs (hi*hi + hi*lo + lo*hi), deg-4 exp poly.
// Delta vs last passing kernel (R2, 194us):
//   - EXPP uses the CORRECT two-step range reduction (t=y+BIG; n=t-BIG exact;
//     f=y-n exact). The round-3 fused form RN(f-BIG)+BIG destroyed f (ulp=1).
//   - GEMM2 accumulators split 3-way (P/Q/R): HMMA dep chains 48 -> 16 deep.
//   - __launch_bounds__(256,3) pins 3 CTAs/SM.
// ============================================================================

#define NBOOK 16
#define DIMS  16
#define KCW   256
#define FDIM  256
#define L2E   1.4426950408889634f

typedef unsigned long long u64;

// Packed codebook: one LDS.128 yields all 4 B fragments (bh0,bh1,bl0,bl1).
//  g_p1: [book][cw][ti]   16B = {h[2ti],h[2ti+1],h[2ti+8],h[2ti+9], l[same]}
//  g_p2: [book][d][m][ti] 16B = same pattern over cw = 16m + {2ti,2ti+1,2ti+8,2ti+9}
__device__ uint4 g_p1[NBOOK * KCW * 4];
__device__ uint4 g_p2[NBOOK * DIMS * 64];

// ---------------------------------------------------------------------------
__global__ void prep_z_kernel(const float* __restrict__ Zw) {
    int b = blockIdx.x, cw = threadIdx.x;
    const float* src = Zw + cw * FDIM + b * DIMS;
    float v[DIMS], ss = 0.f;
#pragma unroll
    for (int d = 0; d < DIMS; d++) { v[d] = src[d]; ss = fmaf(v[d], v[d], ss); }
    float inv = rsqrtf(fmaxf(ss, 1e-24f));   // == 1/clip(norm,1e-12)
    __nv_bfloat16 h[DIMS], l[DIMS];
#pragma unroll
    for (int d = 0; d < DIMS; d++) {
        float z = v[d] * inv;
        h[d] = __float2bfloat16(z);
        l[d] = __float2bfloat16(z - __bfloat162float(h[d]));
    }
    __nv_bfloat16* p1 = (__nv_bfloat16*)(g_p1 + (b * KCW + cw) * 4);
#pragma unroll
    for (int ti = 0; ti < 4; ti++) {
        p1[ti * 8 + 0] = h[2 * ti];     p1[ti * 8 + 1] = h[2 * ti + 1];
        p1[ti * 8 + 2] = h[2 * ti + 8]; p1[ti * 8 + 3] = h[2 * ti + 9];
        p1[ti * 8 + 4] = l[2 * ti];     p1[ti * 8 + 5] = l[2 * ti + 1];
        p1[ti * 8 + 6] = l[2 * ti + 8]; p1[ti * 8 + 7] = l[2 * ti + 9];
    }
    int m = cw >> 4, r = cw & 15;
    int tj = (r >> 1) & 3;
    int slot = (r & 1) + ((r >> 3) << 1);
#pragma unroll
    for (int d = 0; d < DIMS; d++) {
        __nv_bfloat16* q = (__nv_bfloat16*)(g_p2 + ((b * DIMS + d) * 16 + m) * 4 + tj);
        q[slot] = h[d];
        q[slot + 4] = l[d];
    }
}

// ------------------------- packed f32x2 helpers ----------------------------
__device__ __forceinline__ u64 pk2(float lo, float hi) {
    u64 r; asm("mov.b64 %0, {%1,%2};" : "=l"(r) : "f"(lo), "f"(hi)); return r;
}
__device__ __forceinline__ void u2f(u64 v, float& lo, float& hi) {
    asm("mov.b64 {%0,%1}, %2;" : "=f"(lo), "=f"(hi) : "l"(v));
}
__device__ __forceinline__ u64 fma2(u64 a, u64 b, u64 c) {
    u64 d; asm("fma.rn.f32x2 %0, %1, %2, %3;" : "=l"(d) : "l"(a), "l"(b), "l"(c)); return d;
}
__device__ __forceinline__ u64 add2(u64 a, u64 b) {
    u64 d; asm("add.rn.f32x2 %0, %1, %2;" : "=l"(d) : "l"(a), "l"(b)); return d;
}
__device__ __forceinline__ u64 mul2(u64 a, u64 b) {
    u64 d; asm("mul.rn.f32x2 %0, %1, %2;" : "=l"(d) : "l"(a), "l"(b)); return d;
}

__device__ __forceinline__ void mma16816(float* c, const unsigned* a,
                                         unsigned b0, unsigned b1) {
    asm("mma.sync.aligned.m16n8k16.row.col.f32.bf16.bf16.f32 "
        "{%0,%1,%2,%3}, {%4,%5,%6,%7}, {%8,%9}, {%0,%1,%2,%3};"
        : "+f"(c[0]), "+f"(c[1]), "+f"(c[2]), "+f"(c[3])
        : "r"(a[0]), "r"(a[1]), "r"(a[2]), "r"(a[3]), "r"(b0), "r"(b1));
}
__device__ __forceinline__ void mma16816z(float* d, const unsigned* a,
                                          unsigned b0, unsigned b1) {
    asm("mma.sync.aligned.m16n8k16.row.col.f32.bf16.bf16.f32 "
        "{%0,%1,%2,%3}, {%4,%5,%6,%7}, {%8,%9}, {%10,%10,%10,%10};"
        : "=f"(d[0]), "=f"(d[1]), "=f"(d[2]), "=f"(d[3])
        : "r"(a[0]), "r"(a[1]), "r"(a[2]), "r"(a[3]), "r"(b0), "r"(b1), "f"(0.f));
}

// scalar splitpair (prologue only)
__device__ __forceinline__ void splitpair(float a, float b, unsigned& hi, unsigned& lo) {
    unsigned h;
    asm("cvt.rn.bf16x2.f32 %0, %1, %2;" : "=r"(h) : "f"(b), "f"(a));
    float ra = a - __int_as_float(h << 16);
    float rb = b - __int_as_float(h & 0xFFFF0000u);
    unsigned l;
    asm("cvt.rn.bf16x2.f32 %0, %1, %2;" : "=r"(l) : "f"(rb), "f"(ra));
    hi = h; lo = l;
}

// packed exp2 of pair: e = 2^(c*L2E + off). off ensures arg <= 50 always;
// args < -126 flush to 0 via the int-side clamp.
// Range reduction (CORRECT form): t = y+BIG (RN drops frac), n = t-BIG exact,
// f = y-n exact. Do NOT fold the BIG subtraction into the fma: f-BIG has
// ulp=1 and destroys f.
#define EXPP(RES, c0, c1, OFF) do {                                          \
    u64 _y = fma2(pk2((c0), (c1)), K_L2E, (OFF));                            \
    u64 _t = add2(_y, K_BIG);                                                \
    u64 _n = add2(_t, K_NBIG);                                               \
    u64 _f = fma2(_n, K_M1, _y);                                             \
    u64 _p = fma2(K_C4, _f, K_C3);                                           \
    _p = fma2(_p, _f, K_C2);                                                 \
    _p = fma2(_p, _f, K_C1);                                                 \
    _p = fma2(_p, _f, K_ONE);                                                \
    unsigned _i0 = (unsigned)_t, _i1 = (unsigned)(_t >> 32);                 \
    int _e0 = (int)(_i0 - 0x4B3FFF81u); _e0 = _e0 < 0 ? 0 : _e0;             \
    int _e1 = (int)(_i1 - 0x4B3FFF81u); _e1 = _e1 < 0 ? 0 : _e1;             \
    u64 _s = pk2(__int_as_float(_e0 << 23), __int_as_float(_e1 << 23));      \
    RES = mul2(_p, _s);                                                      \
} while (0)

// packed split of an exp pair into bf16x2 hi + bf16x2 lo fragments
#define SPLITP(H, L, E) do {                                                 \
    float _a, _b; u2f((E), _a, _b);                                          \
    unsigned _h;                                                             \
    asm("cvt.rn.bf16x2.f32 %0, %1, %2;" : "=r"(_h) : "f"(_b), "f"(_a));      \
    u64 _hv = pk2(__int_as_float(_h << 16), __int_as_float(_h & 0xFFFF0000u)); \
    u64 _r = fma2(_hv, K_M1, (E));                                           \
    float _ra, _rb; u2f(_r, _ra, _rb);                                       \
    unsigned _l;                                                             \
    asm("cvt.rn.bf16x2.f32 %0, %1, %2;" : "=r"(_l) : "f"(_rb), "f"(_ra));    \
    H = _h; L = _l;                                                          \
} while (0)

// ---------------------------------------------------------------------------
// Main kernel: grid (N/128, 16 books), block 256 (8 warps x 16 rows), 3 CTA/SM.
// ---------------------------------------------------------------------------
__global__ void __launch_bounds__(256, 3)
soft_kernel(const float* __restrict__ feat, const float* __restrict__ alpha_p,
            float* __restrict__ out) {
    __shared__ uint4 s1[KCW * 4];        // 16 KB, stride 64B (conflict-free)
    __shared__ uint4 s2[DIMS * 68];      // 17.4 KB, d-stride 1088B (conflict-free)

    const int tid = threadIdx.x;
    const int book = blockIdx.y;

    {
        const uint4* p1 = g_p1 + book * (KCW * 4);
        const uint4* p2 = g_p2 + book * (DIMS * 64);
        for (int i = tid; i < 1024; i += 256) s1[i] = p1[i];
        for (int i = tid; i < 1024; i += 256) {
            int d = i >> 6, o = i & 63;
            s2[d * 68 + o] = p2[i];
        }
    }
    __syncthreads();

    const float alpha = *alpha_p;
    const int w = tid >> 5, lane = tid & 31;
    const int g = lane >> 2, ti = lane & 3;

    const int row0 = blockIdx.x * 128 + w * 16 + g;      // rows row0, row0+8
    const float* x0 = feat + row0 * FDIM + book * DIMS;
    const float* x1 = x0 + 8 * FDIM;

    // A fragments of alpha*x (split bf16), m16n8k16 layout
    float2 xa = *(const float2*)(x0 + 2 * ti);
    float2 xb = *(const float2*)(x1 + 2 * ti);
    float2 xc = *(const float2*)(x0 + 2 * ti + 8);
    float2 xd = *(const float2*)(x1 + 2 * ti + 8);
    unsigned Ah[4], Al[4];
    splitpair(xa.x * alpha, xa.y * alpha, Ah[0], Al[0]);
    splitpair(xb.x * alpha, xb.y * alpha, Ah[1], Al[1]);
    splitpair(xc.x * alpha, xc.y * alpha, Ah[2], Al[2]);
    splitpair(xd.x * alpha, xd.y * alpha, Ah[3], Al[3]);

    // Cauchy-Schwarz max proxy: off = 50 - alpha*L2E*||x_row||
    float sg0 = xa.x * xa.x + xa.y * xa.y + xc.x * xc.x + xc.y * xc.y;
    float sg1 = xb.x * xb.x + xb.y * xb.y + xd.x * xd.x + xd.y * xd.y;
    sg0 += __shfl_xor_sync(0xffffffffu, sg0, 1);
    sg0 += __shfl_xor_sync(0xffffffffu, sg0, 2);
    sg1 += __shfl_xor_sync(0xffffffffu, sg1, 1);
    sg1 += __shfl_xor_sync(0xffffffffu, sg1, 2);
    float of0 = 50.f - alpha * L2E * sqrtf(sg0);
    float of1 = 50.f - alpha * L2E * sqrtf(sg1);
    const u64 OFF0 = pk2(of0, of0);
    const u64 OFF1 = pk2(of1, of1);

    // packed constants
    const u64 K_L2E  = pk2(L2E, L2E);
    const u64 K_BIG  = pk2(12582912.f, 12582912.f);
    const u64 K_NBIG = pk2(-12582912.f, -12582912.f);
    const u64 K_M1   = pk2(-1.f, -1.f);
    const u64 K_C4   = pk2(9.6181291e-3f, 9.6181291e-3f);
    const u64 K_C3   = pk2(5.5504109e-2f, 5.5504109e-2f);
    const u64 K_C2   = pk2(2.4022651e-1f, 2.4022651e-1f);
    const u64 K_C1   = pk2(6.9314718e-1f, 6.9314718e-1f);
    const u64 K_ONE  = pk2(1.f, 1.f);

    // 3-way split accumulators: P = Eh*Bh, Q = Eh*Bl, R = El*Bh  (per n-half)
    float P0[4] = {0, 0, 0, 0}, Q0[4] = {0, 0, 0, 0}, R0[4] = {0, 0, 0, 0};
    float P1[4] = {0, 0, 0, 0}, Q1[4] = {0, 0, 0, 0}, R1[4] = {0, 0, 0, 0};

    const uint4* b1base = s1 + g * 4 + ti;           // + cw*4
    const uint4* b2g    = s2 + g * 68 + ti;          // + m*4
    const uint4* b2g8   = s2 + (g + 8) * 68 + ti;

#pragma unroll 1
    for (int c = 0; c < 4; c++) {
        // ---- GEMM1 chunk: logits C[8][4] for codewords 64c .. 64c+63 ----
        float C[8][4];
#pragma unroll
        for (int j = 0; j < 8; j++) {
            uint4 B = b1base[(c * 64 + 8 * j) * 4];
            mma16816z(C[j], Ah, B.x, B.y);   // hi*hi (zero-init)
            mma16816 (C[j], Ah, B.z, B.w);   // hi*lo
            mma16816 (C[j], Al, B.x, B.y);   // lo*hi
        }
        // ---- fused exp + GEMM2 accumulate (independent P/Q/R chains) ----
#pragma unroll
        for (int m = 0; m < 4; m++) {
            int mg = c * 4 + m;
            uint4 Bg  = b2g[mg * 4];
            uint4 Bh8 = b2g8[mg * 4];
            u64 E0, E1, E2, E3;
            EXPP(E0, C[2 * m][0],     C[2 * m][1],     OFF0);
            EXPP(E1, C[2 * m][2],     C[2 * m][3],     OFF1);
            EXPP(E2, C[2 * m + 1][0], C[2 * m + 1][1], OFF0);
            EXPP(E3, C[2 * m + 1][2], C[2 * m + 1][3], OFF1);
            unsigned Eh[4], El[4];
            SPLITP(Eh[0], El[0], E0);
            SPLITP(Eh[1], El[1], E1);
            SPLITP(Eh[2], El[2], E2);
            SPLITP(Eh[3], El[3], E3);
            mma16816(P0, Eh, Bg.x, Bg.y);
            mma16816(Q0, Eh, Bg.z, Bg.w);
            mma16816(R0, El, Bg.x, Bg.y);
            mma16816(P1, Eh, Bh8.x, Bh8.y);
            mma16816(Q1, Eh, Bh8.z, Bh8.w);
            mma16816(R1, El, Bh8.x, Bh8.y);
        }
    }

    float D0[4], D1[4];
#pragma unroll
    for (int i = 0; i < 4; i++) {
        D0[i] = P0[i] + Q0[i] + R0[i];
        D1[i] = P1[i] + Q1[i] + R1[i];
    }

    // ---- per-row L2 normalize over 16 dims (softmax denom cancels) ----
    float ss0 = D0[0] * D0[0] + D0[1] * D0[1] + D1[0] * D1[0] + D1[1] * D1[1];
    float ss1 = D0[2] * D0[2] + D0[3] * D0[3] + D1[2] * D1[2] + D1[3] * D1[3];
    ss0 += __shfl_xor_sync(0xffffffffu, ss0, 1);
    ss0 += __shfl_xor_sync(0xffffffffu, ss0, 2);
    ss1 += __shfl_xor_sync(0xffffffffu, ss1, 1);
    ss1 += __shfl_xor_sync(0xffffffffu, ss1, 2);
    float inv0 = rsqrtf(fmaxf(ss0, 1e-24f));
    float inv1 = rsqrtf(fmaxf(ss1, 1e-24f));

    float* o0 = out + row0 * FDIM + book * DIMS;
    float* o1 = o0 + 8 * FDIM;
    *(float2*)(o0 + 2 * ti)     = make_float2(D0[0] * inv0, D0[1] * inv0);
    *(float2*)(o0 + 2 * ti + 8) = make_float2(D1[0] * inv0, D1[1] * inv0);
    *(float2*)(o1 + 2 * ti)     = make_float2(D0[2] * inv1, D0[3] * inv1);
    *(float2*)(o1 + 2 * ti + 8) = make_float2(D1[2] * inv1, D1[3] * inv1);
}

// ---------------------------------------------------------------------------
extern "C" void kernel_launch(void* const* d_in, const int* in_sizes, int n_in,
                              void* d_out, int out_size) {
    const float* feat    = (const float*)d_in[0];
    const float* Zw      = (const float*)d_in[1];
    const float* alpha_p = (const float*)d_in[3];   // d_in[2] = n_book (unused)
    float* out = (float*)d_out;
    int N = in_sizes[0] / FDIM;

    prep_z_kernel<<<NBOOK, KCW>>>(Zw);
    soft_kernel<<<dim3(N / 128, NBOOK), 256>>>(feat, alpha_p, out);
}

// round 7
// speedup vs baseline: 1.0234x; 1.0234x over previous
#include <cuda_runtime.h>
#include <cuda_bf16.h>
#include <cstdint>

// ============================================================================
// softassignment on B200 (sm_100a), round 7 (= round-6 source; round-6 bench
// died to an infra container failure before any HW evidence was produced).
//   out = intranorm( softmax(alpha*<x_b, zhat_bk>) @ zhat_b ), exact identities:
//   - softmax(-a(1-dot)) == softmax(a*dot)
//   - softmax denominator cancels in final per-book L2 norm (never computed)
//   - row offset via Cauchy-Schwarz bound; any COMMON per-row shift cancels in
//     the L2 norm, so the offset may be rounded to an integer and folded into
//     the range-reduction constant BIG.
// Delta vs last passing kernel (R5, 199us) — instruction-count attack; the
// exp/split block is ~87% of issue slots:
//   - A prescaled by alpha*L2E -> MMA output IS y_raw (no per-pair fma2).
//   - t = y + (BIG+round(of)) folds the offset into one add2; n exact.
//   - exponent applied on the int side: r = p_int + (e<<23), replaces
//     shift/pack/mul2; e clamped >= -126 (underflow -> ~0, harmless).
//   - split consumes the two scalar result regs directly (no u2f unpacks).
//   ~26 -> ~21 instrs per exp pair; ~19% fewer total issue slots.
// ============================================================================

#define NBOOK 16
#define DIMS  16
#define KCW   256
#define FDIM  256
#define L2E   1.4426950408889634f

typedef unsigned long long u64;

// Packed codebook: one LDS.128 yields all 4 B fragments (bh0,bh1,bl0,bl1).
__device__ uint4 g_p1[NBOOK * KCW * 4];
__device__ uint4 g_p2[NBOOK * DIMS * 64];

// ---------------------------------------------------------------------------
__global__ void prep_z_kernel(const float* __restrict__ Zw) {
    int b = blockIdx.x, cw = threadIdx.x;
    const float* src = Zw + cw * FDIM + b * DIMS;
    float v[DIMS], ss = 0.f;
#pragma unroll
    for (int d = 0; d < DIMS; d++) { v[d] = src[d]; ss = fmaf(v[d], v[d], ss); }
    float inv = rsqrtf(fmaxf(ss, 1e-24f));   // == 1/clip(norm,1e-12)
    __nv_bfloat16 h[DIMS], l[DIMS];
#pragma unroll
    for (int d = 0; d < DIMS; d++) {
        float z = v[d] * inv;
        h[d] = __float2bfloat16(z);
        l[d] = __float2bfloat16(z - __bfloat162float(h[d]));
    }
    __nv_bfloat16* p1 = (__nv_bfloat16*)(g_p1 + (b * KCW + cw) * 4);
#pragma unroll
    for (int ti = 0; ti < 4; ti++) {
        p1[ti * 8 + 0] = h[2 * ti];     p1[ti * 8 + 1] = h[2 * ti + 1];
        p1[ti * 8 + 2] = h[2 * ti + 8]; p1[ti * 8 + 3] = h[2 * ti + 9];
        p1[ti * 8 + 4] = l[2 * ti];     p1[ti * 8 + 5] = l[2 * ti + 1];
        p1[ti * 8 + 6] = l[2 * ti + 8]; p1[ti * 8 + 7] = l[2 * ti + 9];
    }
    int m = cw >> 4, r = cw & 15;
    int tj = (r >> 1) & 3;
    int slot = (r & 1) + ((r >> 3) << 1);
#pragma unroll
    for (int d = 0; d < DIMS; d++) {
        __nv_bfloat16* q = (__nv_bfloat16*)(g_p2 + ((b * DIMS + d) * 16 + m) * 4 + tj);
        q[slot] = h[d];
        q[slot + 4] = l[d];
    }
}

// ------------------------- packed f32x2 helpers ----------------------------
__device__ __forceinline__ u64 pk2(float lo, float hi) {
    u64 r; asm("mov.b64 %0, {%1,%2};" : "=l"(r) : "f"(lo), "f"(hi)); return r;
}
__device__ __forceinline__ void u2f(u64 v, float& lo, float& hi) {
    asm("mov.b64 {%0,%1}, %2;" : "=f"(lo), "=f"(hi) : "l"(v));
}
__device__ __forceinline__ u64 fma2(u64 a, u64 b, u64 c) {
    u64 d; asm("fma.rn.f32x2 %0, %1, %2, %3;" : "=l"(d) : "l"(a), "l"(b), "l"(c)); return d;
}
__device__ __forceinline__ u64 add2(u64 a, u64 b) {
    u64 d; asm("add.rn.f32x2 %0, %1, %2;" : "=l"(d) : "l"(a), "l"(b)); return d;
}

__device__ __forceinline__ void mma16816(float* c, const unsigned* a,
                                         unsigned b0, unsigned b1) {
    asm("mma.sync.aligned.m16n8k16.row.col.f32.bf16.bf16.f32 "
        "{%0,%1,%2,%3}, {%4,%5,%6,%7}, {%8,%9}, {%0,%1,%2,%3};"
        : "+f"(c[0]), "+f"(c[1]), "+f"(c[2]), "+f"(c[3])
        : "r"(a[0]), "r"(a[1]), "r"(a[2]), "r"(a[3]), "r"(b0), "r"(b1));
}
__device__ __forceinline__ void mma16816z(float* d, const unsigned* a,
                                          unsigned b0, unsigned b1) {
    asm("mma.sync.aligned.m16n8k16.row.col.f32.bf16.bf16.f32 "
        "{%0,%1,%2,%3}, {%4,%5,%6,%7}, {%8,%9}, {%10,%10,%10,%10};"
        : "=f"(d[0]), "=f"(d[1]), "=f"(d[2]), "=f"(d[3])
        : "r"(a[0]), "r"(a[1]), "r"(a[2]), "r"(a[3]), "r"(b0), "r"(b1), "f"(0.f));
}

// scalar splitpair (prologue only)
__device__ __forceinline__ void splitpair(float a, float b, unsigned& hi, unsigned& lo) {
    unsigned h;
    asm("cvt.rn.bf16x2.f32 %0, %1, %2;" : "=r"(h) : "f"(b), "f"(a));
    float ra = a - __int_as_float(h << 16);
    float rb = b - __int_as_float(h & 0xFFFF0000u);
    unsigned l;
    asm("cvt.rn.bf16x2.f32 %0, %1, %2;" : "=r"(l) : "f"(rb), "f"(ra));
    hi = h; lo = l;
}

// Fused exp2 + bf16 hi/lo split of a logit pair.
//   y = c (already includes alpha*L2E via A prescale)
//   t = y + KBO where KBO = BIG + round(offset): RN drops the fraction of
//     (y+offset); n = t + KNBO (= t-KBO) is EXACT; f = y - n is EXACT.
//   exponent applied integer-side: r = p_int + (e<<23), e = ib-0x4B400000,
//     clamped at -126 (result ~2^-126, harmless; prevents sign-bit wrap).
#define EXPSPLIT(EH, EL, c0, c1, KBO, KNBO) do {                             \
    u64 _y = pk2((c0), (c1));                                                \
    u64 _t = add2(_y, (KBO));                                                \
    u64 _n = add2(_t, (KNBO));                                               \
    u64 _f = fma2(_n, K_M1, _y);                                             \
    u64 _p = fma2(K_C4, _f, K_C3);                                           \
    _p = fma2(_p, _f, K_C2);                                                 \
    _p = fma2(_p, _f, K_C1);                                                 \
    _p = fma2(_p, _f, K_ONE);                                                \
    int _e0 = (int)(unsigned)_t - 0x4B400000;                                \
    int _e1 = (int)(unsigned)(_t >> 32) - 0x4B400000;                        \
    _e0 = _e0 < -126 ? -126 : _e0;                                           \
    _e1 = _e1 < -126 ? -126 : _e1;                                           \
    unsigned _r0 = (unsigned)(int)(unsigned)_p + ((unsigned)_e0 << 23);      \
    unsigned _r1 = (unsigned)(int)(unsigned)(_p >> 32) + ((unsigned)_e1 << 23);\
    asm("cvt.rn.bf16x2.f32 %0, %1, %2;" : "=r"(EH)                           \
        : "f"(__uint_as_float(_r1)), "f"(__uint_as_float(_r0)));             \
    u64 _hv = pk2(__uint_as_float((EH) << 16),                               \
                  __uint_as_float((EH) & 0xFFFF0000u));                      \
    u64 _el = fma2(_hv, K_M1, pk2(__uint_as_float(_r0),                      \
                                  __uint_as_float(_r1)));                    \
    float _ea, _eb; u2f(_el, _ea, _eb);                                      \
    asm("cvt.rn.bf16x2.f32 %0, %1, %2;" : "=r"(EL) : "f"(_eb), "f"(_ea));    \
} while (0)

// ---------------------------------------------------------------------------
// Main kernel: grid (N/128, 16 books), block 256 (8 warps x 16 rows), 3 CTA/SM.
// ---------------------------------------------------------------------------
__global__ void __launch_bounds__(256, 3)
soft_kernel(const float* __restrict__ feat, const float* __restrict__ alpha_p,
            float* __restrict__ out) {
    __shared__ uint4 s1[KCW * 4];        // 16 KB, stride 64B (conflict-free)
    __shared__ uint4 s2[DIMS * 68];      // 17.4 KB, d-stride 1088B (conflict-free)

    const int tid = threadIdx.x;
    const int book = blockIdx.y;

    {
        const uint4* p1 = g_p1 + book * (KCW * 4);
        const uint4* p2 = g_p2 + book * (DIMS * 64);
        for (int i = tid; i < 1024; i += 256) s1[i] = p1[i];
        for (int i = tid; i < 1024; i += 256) {
            int d = i >> 6, o = i & 63;
            s2[d * 68 + o] = p2[i];
        }
    }
    __syncthreads();

    const float scale = *alpha_p * L2E;       // alpha*log2(e) folded into A
    const int w = tid >> 5, lane = tid & 31;
    const int g = lane >> 2, ti = lane & 3;

    const int row0 = blockIdx.x * 128 + w * 16 + g;      // rows row0, row0+8
    const float* x0 = feat + row0 * FDIM + book * DIMS;
    const float* x1 = x0 + 8 * FDIM;

    // A fragments of (alpha*L2E)*x (split bf16), m16n8k16 layout
    float2 xa = *(const float2*)(x0 + 2 * ti);
    float2 xb = *(const float2*)(x1 + 2 * ti);
    float2 xc = *(const float2*)(x0 + 2 * ti + 8);
    float2 xd = *(const float2*)(x1 + 2 * ti + 8);
    unsigned Ah[4], Al[4];
    splitpair(xa.x * scale, xa.y * scale, Ah[0], Al[0]);
    splitpair(xb.x * scale, xb.y * scale, Ah[1], Al[1]);
    splitpair(xc.x * scale, xc.y * scale, Ah[2], Al[2]);
    splitpair(xd.x * scale, xd.y * scale, Ah[3], Al[3]);

    // Cauchy-Schwarz offset: of = 50 - scale*||x_row||  (y_raw <= scale*||x||)
    float sg0 = xa.x * xa.x + xa.y * xa.y + xc.x * xc.x + xc.y * xc.y;
    float sg1 = xb.x * xb.x + xb.y * xb.y + xd.x * xd.x + xd.y * xd.y;
    sg0 += __shfl_xor_sync(0xffffffffu, sg0, 1);
    sg0 += __shfl_xor_sync(0xffffffffu, sg0, 2);
    sg1 += __shfl_xor_sync(0xffffffffu, sg1, 1);
    sg1 += __shfl_xor_sync(0xffffffffu, sg1, 2);
    float bo0 = 12582912.f + (50.f - scale * sqrtf(sg0));  // BIG+of, of->int
    float bo1 = 12582912.f + (50.f - scale * sqrtf(sg1));
    const u64 K_BO0  = pk2(bo0, bo0);
    const u64 K_NBO0 = pk2(-bo0, -bo0);
    const u64 K_BO1  = pk2(bo1, bo1);
    const u64 K_NBO1 = pk2(-bo1, -bo1);

    // packed constants
    const u64 K_M1   = pk2(-1.f, -1.f);
    const u64 K_C4   = pk2(9.6181291e-3f, 9.6181291e-3f);
    const u64 K_C3   = pk2(5.5504109e-2f, 5.5504109e-2f);
    const u64 K_C2   = pk2(2.4022651e-1f, 2.4022651e-1f);
    const u64 K_C1   = pk2(6.9314718e-1f, 6.9314718e-1f);
    const u64 K_ONE  = pk2(1.f, 1.f);

    // 3-way split accumulators: P = Eh*Bh, Q = Eh*Bl, R = El*Bh  (per n-half)
    float P0[4] = {0, 0, 0, 0}, Q0[4] = {0, 0, 0, 0}, R0[4] = {0, 0, 0, 0};
    float P1[4] = {0, 0, 0, 0}, Q1[4] = {0, 0, 0, 0}, R1[4] = {0, 0, 0, 0};

    const uint4* b1base = s1 + g * 4 + ti;           // + cw*4
    const uint4* b2g    = s2 + g * 68 + ti;          // + m*4
    const uint4* b2g8   = s2 + (g + 8) * 68 + ti;

#pragma unroll 1
    for (int c = 0; c < 4; c++) {
        // ---- GEMM1 chunk: y_raw C[8][4] for codewords 64c .. 64c+63 ----
        float C[8][4];
#pragma unroll
        for (int j = 0; j < 8; j++) {
            uint4 B = b1base[(c * 64 + 8 * j) * 4];
            mma16816z(C[j], Ah, B.x, B.y);   // hi*hi (zero-init)
            mma16816 (C[j], Ah, B.z, B.w);   // hi*lo
            mma16816 (C[j], Al, B.x, B.y);   // lo*hi
        }
        // ---- fused exp + GEMM2 accumulate ----
#pragma unroll
        for (int m = 0; m < 4; m++) {
            int mg = c * 4 + m;
            uint4 Bg  = b2g[mg * 4];
            uint4 Bh8 = b2g8[mg * 4];
            unsigned Eh[4], El[4];
            EXPSPLIT(Eh[0], El[0], C[2 * m][0],     C[2 * m][1],     K_BO0, K_NBO0);
            EXPSPLIT(Eh[1], El[1], C[2 * m][2],     C[2 * m][3],     K_BO1, K_NBO1);
            EXPSPLIT(Eh[2], El[2], C[2 * m + 1][0], C[2 * m + 1][1], K_BO0, K_NBO0);
            EXPSPLIT(Eh[3], El[3], C[2 * m + 1][2], C[2 * m + 1][3], K_BO1, K_NBO1);
            mma16816(P0, Eh, Bg.x, Bg.y);
            mma16816(Q0, Eh, Bg.z, Bg.w);
            mma16816(R0, El, Bg.x, Bg.y);
            mma16816(P1, Eh, Bh8.x, Bh8.y);
            mma16816(Q1, Eh, Bh8.z, Bh8.w);
            mma16816(R1, El, Bh8.x, Bh8.y);
        }
    }

    float D0[4], D1[4];
#pragma unroll
    for (int i = 0; i < 4; i++) {
        D0[i] = P0[i] + Q0[i] + R0[i];
        D1[i] = P1[i] + Q1[i] + R1[i];
    }

    // ---- per-row L2 normalize over 16 dims (softmax denom cancels) ----
    float ss0 = D0[0] * D0[0] + D0[1] * D0[1] + D1[0] * D1[0] + D1[1] * D1[1];
    float ss1 = D0[2] * D0[2] + D0[3] * D0[3] + D1[2] * D1[2] + D1[3] * D1[3];
    ss0 += __shfl_xor_sync(0xffffffffu, ss0, 1);
    ss0 += __shfl_xor_sync(0xffffffffu, ss0, 2);
    ss1 += __shfl_xor_sync(0xffffffffu, ss1, 1);
    ss1 += __shfl_xor_sync(0xffffffffu, ss1, 2);
    float inv0 = rsqrtf(fmaxf(ss0, 1e-24f));
    float inv1 = rsqrtf(fmaxf(ss1, 1e-24f));

    float* o0 = out + row0 * FDIM + book * DIMS;
    float* o1 = o0 + 8 * FDIM;
    *(float2*)(o0 + 2 * ti)     = make_float2(D0[0] * inv0, D0[1] * inv0);
    *(float2*)(o0 + 2 * ti + 8) = make_float2(D1[0] * inv0, D1[1] * inv0);
    *(float2*)(o1 + 2 * ti)     = make_float2(D0[2] * inv1, D0[3] * inv1);
    *(float2*)(o1 + 2 * ti + 8) = make_float2(D1[2] * inv1, D1[3] * inv1);
}

// ---------------------------------------------------------------------------
extern "C" void kernel_launch(void* const* d_in, const int* in_sizes, int n_in,
                              void* d_out, int out_size) {
    const float* feat    = (const float*)d_in[0];
    const float* Zw      = (const float*)d_in[1];
    const float* alpha_p = (const float*)d_in[3];   // d_in[2] = n_book (unused)
    float* out = (float*)d_out;
    int N = in_sizes[0] / FDIM;

    prep_z_kernel<<<NBOOK, KCW>>>(Zw);
    soft_kernel<<<dim3(N / 128, NBOOK), 256>>>(feat, alpha_p, out);
}

// round 9
// speedup vs baseline: 1.2309x; 1.2028x over previous
#include <cuda_runtime.h>
#include <cuda_bf16.h>
#include <cstdint>

// ============================================================================
// softassignment on B200 (sm_100a), round 9 (= round-8 source; round-8 bench
// died to an infra container failure before any HW evidence was produced).
//   out = intranorm( softmax(alpha*<x_b, zhat_bk>) @ zhat_b ), exact identities:
//   - softmax(-a(1-dot)) == softmax(a*dot); denominator cancels in final L2.
//   - per-row overflow guard (Cauchy-Schwarz) folded into the MMA accumulator
//     INIT of GEMM1 (C-input = offset), so logits emerge pre-shifted. Any
//     common per-row shift cancels in the final L2 norm.
// Round-8/9 delta — move exp off the FP32 pipes entirely:
//   f32x2 packed math gives NO pipe throughput on sm_100 (16 FP32 lanes/SMSP;
//   FFMA2 rt=4 = 2x FFMA), which is why rounds 2-7 were all ~195us: the exp
//   poly's fma-pipe cycles never changed. MUFU.EX2 instead: 268M exps = only
//   ~63us of SFU pipe (rt 8/SMSP, 592 SMSPs) — a pipe that was 100% idle.
//   Exp block: 21 instrs/pair -> ~8 (2x ex2.approx + scalar bf16 split).
//   Tensor pipe becomes the binder (~100-115us predicted).
// Precision: 3-term split-bf16 MMAs both GEMMs; ex2.approx ~1-2 ulp.
// ============================================================================

#define NBOOK 16
#define DIMS  16
#define KCW   256
#define FDIM  256
#define L2E   1.4426950408889634f

// Packed codebook: one LDS.128 yields all 4 B fragments (bh0,bh1,bl0,bl1).
//  g_p1: [book][cw][ti]   16B = {h[2ti],h[2ti+1],h[2ti+8],h[2ti+9], l[same]}
//  g_p2: [book][d][m][ti] 16B = same over cw = 16m + {2ti,2ti+1,2ti+8,2ti+9}
__device__ uint4 g_p1[NBOOK * KCW * 4];
__device__ uint4 g_p2[NBOOK * DIMS * 64];

// ---------------------------------------------------------------------------
__global__ void prep_z_kernel(const float* __restrict__ Zw) {
    int b = blockIdx.x, cw = threadIdx.x;
    const float* src = Zw + cw * FDIM + b * DIMS;
    float v[DIMS], ss = 0.f;
#pragma unroll
    for (int d = 0; d < DIMS; d++) { v[d] = src[d]; ss = fmaf(v[d], v[d], ss); }
    float inv = rsqrtf(fmaxf(ss, 1e-24f));   // == 1/clip(norm,1e-12)
    __nv_bfloat16 h[DIMS], l[DIMS];
#pragma unroll
    for (int d = 0; d < DIMS; d++) {
        float z = v[d] * inv;
        h[d] = __float2bfloat16(z);
        l[d] = __float2bfloat16(z - __bfloat162float(h[d]));
    }
    __nv_bfloat16* p1 = (__nv_bfloat16*)(g_p1 + (b * KCW + cw) * 4);
#pragma unroll
    for (int ti = 0; ti < 4; ti++) {
        p1[ti * 8 + 0] = h[2 * ti];     p1[ti * 8 + 1] = h[2 * ti + 1];
        p1[ti * 8 + 2] = h[2 * ti + 8]; p1[ti * 8 + 3] = h[2 * ti + 9];
        p1[ti * 8 + 4] = l[2 * ti];     p1[ti * 8 + 5] = l[2 * ti + 1];
        p1[ti * 8 + 6] = l[2 * ti + 8]; p1[ti * 8 + 7] = l[2 * ti + 9];
    }
    int m = cw >> 4, r = cw & 15;
    int tj = (r >> 1) & 3;
    int slot = (r & 1) + ((r >> 3) << 1);
#pragma unroll
    for (int d = 0; d < DIMS; d++) {
        __nv_bfloat16* q = (__nv_bfloat16*)(g_p2 + ((b * DIMS + d) * 16 + m) * 4 + tj);
        q[slot] = h[d];
        q[slot + 4] = l[d];
    }
}

// ---------------------------------------------------------------------------
__device__ __forceinline__ void mma16816(float* c, const unsigned* a,
                                         unsigned b0, unsigned b1) {
    asm("mma.sync.aligned.m16n8k16.row.col.f32.bf16.bf16.f32 "
        "{%0,%1,%2,%3}, {%4,%5,%6,%7}, {%8,%9}, {%0,%1,%2,%3};"
        : "+f"(c[0]), "+f"(c[1]), "+f"(c[2]), "+f"(c[3])
        : "r"(a[0]), "r"(a[1]), "r"(a[2]), "r"(a[3]), "r"(b0), "r"(b1));
}
// first MMA of a chain: C-input supplied (per-row offsets ride in for free)
__device__ __forceinline__ void mma16816i(float* d, const unsigned* a,
                                          unsigned b0, unsigned b1,
                                          float i0, float i1, float i2, float i3) {
    asm("mma.sync.aligned.m16n8k16.row.col.f32.bf16.bf16.f32 "
        "{%0,%1,%2,%3}, {%4,%5,%6,%7}, {%8,%9}, {%10,%11,%12,%13};"
        : "=f"(d[0]), "=f"(d[1]), "=f"(d[2]), "=f"(d[3])
        : "r"(a[0]), "r"(a[1]), "r"(a[2]), "r"(a[3]), "r"(b0), "r"(b1),
          "f"(i0), "f"(i1), "f"(i2), "f"(i3));
}

// scalar splitpair (prologue only)
__device__ __forceinline__ void splitpair(float a, float b, unsigned& hi, unsigned& lo) {
    unsigned h;
    asm("cvt.rn.bf16x2.f32 %0, %1, %2;" : "=r"(h) : "f"(b), "f"(a));
    float ra = a - __int_as_float(h << 16);
    float rb = b - __int_as_float(h & 0xFFFF0000u);
    unsigned l;
    asm("cvt.rn.bf16x2.f32 %0, %1, %2;" : "=r"(l) : "f"(rb), "f"(ra));
    hi = h; lo = l;
}

// exp2 on the SFU pipe + bf16 hi/lo split. c0,c1 are pre-offset log2-domain
// logits (offset guarantees arg <= 50: no overflow; deep negative -> 0).
#define EXPB(EH, EL, c0, c1) do {                                            \
    float _e0, _e1;                                                          \
    asm("ex2.approx.ftz.f32 %0, %1;" : "=f"(_e0) : "f"(c0));                 \
    asm("ex2.approx.ftz.f32 %0, %1;" : "=f"(_e1) : "f"(c1));                 \
    asm("cvt.rn.bf16x2.f32 %0, %1, %2;" : "=r"(EH) : "f"(_e1), "f"(_e0));    \
    float _r0 = _e0 - __uint_as_float((EH) << 16);                           \
    float _r1 = _e1 - __uint_as_float((EH) & 0xFFFF0000u);                   \
    asm("cvt.rn.bf16x2.f32 %0, %1, %2;" : "=r"(EL) : "f"(_r1), "f"(_r0));    \
} while (0)

// ---------------------------------------------------------------------------
// Main kernel: grid (N/128, 16 books), block 256 (8 warps x 16 rows), 3 CTA/SM.
// ---------------------------------------------------------------------------
__global__ void __launch_bounds__(256, 3)
soft_kernel(const float* __restrict__ feat, const float* __restrict__ alpha_p,
            float* __restrict__ out) {
    __shared__ uint4 s1[KCW * 4];        // 16 KB, stride 64B (conflict-free)
    __shared__ uint4 s2[DIMS * 68];      // 17.4 KB, d-stride 1088B (conflict-free)

    const int tid = threadIdx.x;
    const int book = blockIdx.y;

    {
        const uint4* p1 = g_p1 + book * (KCW * 4);
        const uint4* p2 = g_p2 + book * (DIMS * 64);
        for (int i = tid; i < 1024; i += 256) s1[i] = p1[i];
        for (int i = tid; i < 1024; i += 256) {
            int d = i >> 6, o = i & 63;
            s2[d * 68 + o] = p2[i];
        }
    }
    __syncthreads();

    const float scale = *alpha_p * L2E;       // alpha*log2(e) folded into A
    const int w = tid >> 5, lane = tid & 31;
    const int g = lane >> 2, ti = lane & 3;

    const int row0 = blockIdx.x * 128 + w * 16 + g;      // rows row0, row0+8
    const float* x0 = feat + row0 * FDIM + book * DIMS;
    const float* x1 = x0 + 8 * FDIM;

    // A fragments of (alpha*L2E)*x (split bf16), m16n8k16 layout
    float2 xa = *(const float2*)(x0 + 2 * ti);
    float2 xb = *(const float2*)(x1 + 2 * ti);
    float2 xc = *(const float2*)(x0 + 2 * ti + 8);
    float2 xd = *(const float2*)(x1 + 2 * ti + 8);
    unsigned Ah[4], Al[4];
    splitpair(xa.x * scale, xa.y * scale, Ah[0], Al[0]);
    splitpair(xb.x * scale, xb.y * scale, Ah[1], Al[1]);
    splitpair(xc.x * scale, xc.y * scale, Ah[2], Al[2]);
    splitpair(xd.x * scale, xd.y * scale, Ah[3], Al[3]);

    // Cauchy-Schwarz offset: of = 50 - scale*||x_row||  (=> logit+of <= 50)
    float sg0 = xa.x * xa.x + xa.y * xa.y + xc.x * xc.x + xc.y * xc.y;
    float sg1 = xb.x * xb.x + xb.y * xb.y + xd.x * xd.x + xd.y * xd.y;
    sg0 += __shfl_xor_sync(0xffffffffu, sg0, 1);
    sg0 += __shfl_xor_sync(0xffffffffu, sg0, 2);
    sg1 += __shfl_xor_sync(0xffffffffu, sg1, 1);
    sg1 += __shfl_xor_sync(0xffffffffu, sg1, 2);
    const float of0 = 50.f - scale * sqrtf(sg0);
    const float of1 = 50.f - scale * sqrtf(sg1);

    // 3-way split accumulators: P = Eh*Bh, Q = Eh*Bl, R = El*Bh  (per n-half)
    float P0[4] = {0, 0, 0, 0}, Q0[4] = {0, 0, 0, 0}, R0[4] = {0, 0, 0, 0};
    float P1[4] = {0, 0, 0, 0}, Q1[4] = {0, 0, 0, 0}, R1[4] = {0, 0, 0, 0};

    const uint4* b1base = s1 + g * 4 + ti;           // + cw*4
    const uint4* b2g    = s2 + g * 68 + ti;          // + m*4
    const uint4* b2g8   = s2 + (g + 8) * 68 + ti;

#pragma unroll 1
    for (int c = 0; c < 4; c++) {
        // ---- GEMM1 chunk: offset + logits, C[8][4], codewords 64c..64c+63 ----
        float C[8][4];
#pragma unroll
        for (int j = 0; j < 8; j++) {
            uint4 B = b1base[(c * 64 + 8 * j) * 4];
            mma16816i(C[j], Ah, B.x, B.y, of0, of0, of1, of1);  // hi*hi + off
            mma16816 (C[j], Ah, B.z, B.w);                      // hi*lo
            mma16816 (C[j], Al, B.x, B.y);                      // lo*hi
        }
        // ---- exp on SFU pipe + GEMM2 accumulate ----
#pragma unroll
        for (int m = 0; m < 4; m++) {
            int mg = c * 4 + m;
            uint4 Bg  = b2g[mg * 4];
            uint4 Bh8 = b2g8[mg * 4];
            unsigned Eh[4], El[4];
            EXPB(Eh[0], El[0], C[2 * m][0],     C[2 * m][1]);
            EXPB(Eh[1], El[1], C[2 * m][2],     C[2 * m][3]);
            EXPB(Eh[2], El[2], C[2 * m + 1][0], C[2 * m + 1][1]);
            EXPB(Eh[3], El[3], C[2 * m + 1][2], C[2 * m + 1][3]);
            mma16816(P0, Eh, Bg.x, Bg.y);
            mma16816(Q0, Eh, Bg.z, Bg.w);
            mma16816(R0, El, Bg.x, Bg.y);
            mma16816(P1, Eh, Bh8.x, Bh8.y);
            mma16816(Q1, Eh, Bh8.z, Bh8.w);
            mma16816(R1, El, Bh8.x, Bh8.y);
        }
    }

    float D0[4], D1[4];
#pragma unroll
    for (int i = 0; i < 4; i++) {
        D0[i] = P0[i] + Q0[i] + R0[i];
        D1[i] = P1[i] + Q1[i] + R1[i];
    }

    // ---- per-row L2 normalize over 16 dims (softmax denom cancels) ----
    float ss0 = D0[0] * D0[0] + D0[1] * D0[1] + D1[0] * D1[0] + D1[1] * D1[1];
    float ss1 = D0[2] * D0[2] + D0[3] * D0[3] + D1[2] * D1[2] + D1[3] * D1[3];
    ss0 += __shfl_xor_sync(0xffffffffu, ss0, 1);
    ss0 += __shfl_xor_sync(0xffffffffu, ss0, 2);
    ss1 += __shfl_xor_sync(0xffffffffu, ss1, 1);
    ss1 += __shfl_xor_sync(0xffffffffu, ss1, 2);
    float inv0 = rsqrtf(fmaxf(ss0, 1e-24f));
    float inv1 = rsqrtf(fmaxf(ss1, 1e-24f));

    float* o0 = out + row0 * FDIM + book * DIMS;
    float* o1 = o0 + 8 * FDIM;
    *(float2*)(o0 + 2 * ti)     = make_float2(D0[0] * inv0, D0[1] * inv0);
    *(float2*)(o0 + 2 * ti + 8) = make_float2(D1[0] * inv0, D1[1] * inv0);
    *(float2*)(o1 + 2 * ti)     = make_float2(D0[2] * inv1, D0[3] * inv1);
    *(float2*)(o1 + 2 * ti + 8) = make_float2(D1[2] * inv1, D1[3] * inv1);
}

// ---------------------------------------------------------------------------
extern "C" void kernel_launch(void* const* d_in, const int* in_sizes, int n_in,
                              void* d_out, int out_size) {
    const float* feat    = (const float*)d_in[0];
    const float* Zw      = (const float*)d_in[1];
    const float* alpha_p = (const float*)d_in[3];   // d_in[2] = n_book (unused)
    float* out = (float*)d_out;
    int N = in_sizes[0] / FDIM;

    prep_z_kernel<<<NBOOK, KCW>>>(Zw);
    soft_kernel<<<dim3(N / 128, NBOOK), 256>>>(feat, alpha_p, out);
}

// round 13
// speedup vs baseline: 1.4692x; 1.1936x over previous
#include <cuda_runtime.h>
#include <cuda_bf16.h>
#include <cuda_fp16.h>
#include <cstdint>

// ============================================================================
// softassignment on B200 (sm_100a), round 13.
//   out = intranorm( softmax(alpha*<x_b, zhat_bk>) @ zhat_b )
//   - softmax(-a(1-dot)) == softmax(a*dot); denominator cancels in final L2.
//   - exp on the SFU pipe (ex2.approx.ftz)  [R9 win].
//   - GEMM2 single fp16 MMA (-33% tensor work vs R9)  [R12 goal].
// Round-13 delta — R12 failed (2.9e-2) because the STATIC Cauchy-Schwarz
// offset is loose by 20-30 log2 units on unlucky rows, pushing the dominant
// fp16 weights into the subnormal zone (normals end at 2^-14). Fix: ONLINE
// per-chunk row max with accumulator rescaling (flash-attention style):
//   - after each GEMM1 chunk: m_c = exact row max (regs+2 shfls),
//     M = max(M, m_c); D *= 2^(M_old - M) (SFU ex2); bias = 14 - M.
//   - exp arg = logit + bias  =>  max weight EXACTLY 2^14: every weight
//     within 2^-28 of max is a normal fp16 (full 11-bit mantissa).
//   - common per-row scale 2^(14-M) cancels in the final L2 norm.
// Error budget (measurement-anchored): codebook fp16 1.35e-3/8 ~ 1.7e-4
// (R11 scaled), weight fp16 ~2^-12 ~ 1-2e-4  =>  ~3e-4 total.
// GEMM1 unchanged (3-term split bf16; its error enters the exponent).
// ============================================================================

#define NBOOK 16
#define DIMS  16
#define KCW   256
#define FDIM  256
#define L2E   1.4426950408889634f

// g_p1 (GEMM1 B, bf16 hi/lo): [book][cw][ti] 16B, one LDS.128 = 4 fragments.
// g_p2 (GEMM2 B, fp16):       [book][d<8][m][ti] 16B =
//   {f16x2(z[d][16m+2ti..]), f16x2(z[d][16m+2ti+8..]), same for d+8}
__device__ uint4 g_p1[NBOOK * KCW * 4];
__device__ uint4 g_p2[NBOOK * 512];

// ---------------------------------------------------------------------------
__global__ void prep_z_kernel(const float* __restrict__ Zw) {
    int b = blockIdx.x, cw = threadIdx.x;
    const float* src = Zw + cw * FDIM + b * DIMS;
    float v[DIMS], ss = 0.f;
#pragma unroll
    for (int d = 0; d < DIMS; d++) { v[d] = src[d]; ss = fmaf(v[d], v[d], ss); }
    float inv = rsqrtf(fmaxf(ss, 1e-24f));   // == 1/clip(norm,1e-12)
    float z[DIMS];
    __nv_bfloat16 h[DIMS], l[DIMS];
#pragma unroll
    for (int d = 0; d < DIMS; d++) {
        z[d] = v[d] * inv;
        h[d] = __float2bfloat16(z[d]);
        l[d] = __float2bfloat16(z[d] - __bfloat162float(h[d]));
    }
    __nv_bfloat16* p1 = (__nv_bfloat16*)(g_p1 + (b * KCW + cw) * 4);
#pragma unroll
    for (int ti = 0; ti < 4; ti++) {
        p1[ti * 8 + 0] = h[2 * ti];     p1[ti * 8 + 1] = h[2 * ti + 1];
        p1[ti * 8 + 2] = h[2 * ti + 8]; p1[ti * 8 + 3] = h[2 * ti + 9];
        p1[ti * 8 + 4] = l[2 * ti];     p1[ti * 8 + 5] = l[2 * ti + 1];
        p1[ti * 8 + 6] = l[2 * ti + 8]; p1[ti * 8 + 7] = l[2 * ti + 9];
    }
    // GEMM2 fp16 packing: cw = 16m + r; slot = (r&1)+((r>>3)<<1) encodes
    // k-order {2ti, 2ti+1, 2ti+8, 2ti+9}.
    int m = cw >> 4, r = cw & 15;
    int tj = (r >> 1) & 3;
    int slot = (r & 1) + ((r >> 3) << 1);
#pragma unroll
    for (int d = 0; d < 8; d++) {
        __half* q = (__half*)(g_p2 + ((b * 8 + d) * 16 + m) * 4 + tj);
        q[slot]     = __float2half_rn(z[d]);
        q[slot + 4] = __float2half_rn(z[d + 8]);
    }
}

// ---------------------------------------------------------------------------
__device__ __forceinline__ void mma16816(float* c, const unsigned* a,
                                         unsigned b0, unsigned b1) {
    asm("mma.sync.aligned.m16n8k16.row.col.f32.bf16.bf16.f32 "
        "{%0,%1,%2,%3}, {%4,%5,%6,%7}, {%8,%9}, {%0,%1,%2,%3};"
        : "+f"(c[0]), "+f"(c[1]), "+f"(c[2]), "+f"(c[3])
        : "r"(a[0]), "r"(a[1]), "r"(a[2]), "r"(a[3]), "r"(b0), "r"(b1));
}
__device__ __forceinline__ void mma16816z(float* d, const unsigned* a,
                                          unsigned b0, unsigned b1) {
    asm("mma.sync.aligned.m16n8k16.row.col.f32.bf16.bf16.f32 "
        "{%0,%1,%2,%3}, {%4,%5,%6,%7}, {%8,%9}, {%10,%10,%10,%10};"
        : "=f"(d[0]), "=f"(d[1]), "=f"(d[2]), "=f"(d[3])
        : "r"(a[0]), "r"(a[1]), "r"(a[2]), "r"(a[3]), "r"(b0), "r"(b1), "f"(0.f));
}
// fp16 variant for GEMM2
__device__ __forceinline__ void mma16816h(float* c, const unsigned* a,
                                          unsigned b0, unsigned b1) {
    asm("mma.sync.aligned.m16n8k16.row.col.f32.f16.f16.f32 "
        "{%0,%1,%2,%3}, {%4,%5,%6,%7}, {%8,%9}, {%0,%1,%2,%3};"
        : "+f"(c[0]), "+f"(c[1]), "+f"(c[2]), "+f"(c[3])
        : "r"(a[0]), "r"(a[1]), "r"(a[2]), "r"(a[3]), "r"(b0), "r"(b1));
}

// scalar splitpair (prologue only)
__device__ __forceinline__ void splitpair(float a, float b, unsigned& hi, unsigned& lo) {
    unsigned h;
    asm("cvt.rn.bf16x2.f32 %0, %1, %2;" : "=r"(h) : "f"(b), "f"(a));
    float ra = a - __int_as_float(h << 16);
    float rb = b - __int_as_float(h & 0xFFFF0000u);
    unsigned l;
    asm("cvt.rn.bf16x2.f32 %0, %1, %2;" : "=r"(l) : "f"(rb), "f"(ra));
    hi = h; lo = l;
}

__device__ __forceinline__ float ex2f(float x) {
    float r;
    asm("ex2.approx.ftz.f32 %0, %1;" : "=f"(r) : "f"(x));
    return r;
}

// exp2(c + bias) on SFU + pack pair to f16x2. bias = 14 - rowmax, so the
// max weight is exactly 2^14 (fp16-normal down to 2^-14: 28-bit usable span).
#define EXPH(EH, c0, c1, bias) do {                                          \
    float _e0 = ex2f((c0) + (bias));                                         \
    float _e1 = ex2f((c1) + (bias));                                         \
    asm("cvt.rn.f16x2.f32 %0, %1, %2;" : "=r"(EH) : "f"(_e1), "f"(_e0));     \
} while (0)

// ---------------------------------------------------------------------------
// Main kernel: grid (N/128, 16 books), block 256 (8 warps x 16 rows), 3 CTA/SM.
// ---------------------------------------------------------------------------
__global__ void __launch_bounds__(256, 3)
soft_kernel(const float* __restrict__ feat, const float* __restrict__ alpha_p,
            float* __restrict__ out) {
    __shared__ uint4 s1[KCW * 4];        // 16 KB, stride 64B (conflict-free)
    __shared__ uint4 s2[8 * 68];         // 8.7 KB, d-stride 68*16B (conflict-free)

    const int tid = threadIdx.x;
    const int book = blockIdx.y;

    {
        const uint4* p1 = g_p1 + book * (KCW * 4);
        const uint4* p2 = g_p2 + book * 512;
        for (int i = tid; i < 1024; i += 256) s1[i] = p1[i];
        for (int i = tid; i < 512; i += 256) {
            int d = i >> 6, o = i & 63;          // o = m*4 + ti
            s2[d * 68 + o] = p2[i];
        }
    }
    __syncthreads();

    const float scale = *alpha_p * L2E;       // alpha*log2(e) folded into A
    const int w = tid >> 5, lane = tid & 31;
    const int g = lane >> 2, ti = lane & 3;

    const int row0 = blockIdx.x * 128 + w * 16 + g;      // rows row0, row0+8
    const float* x0 = feat + row0 * FDIM + book * DIMS;
    const float* x1 = x0 + 8 * FDIM;

    // A fragments of (alpha*L2E)*x (split bf16), m16n8k16 layout
    float2 xa = *(const float2*)(x0 + 2 * ti);
    float2 xb = *(const float2*)(x1 + 2 * ti);
    float2 xc = *(const float2*)(x0 + 2 * ti + 8);
    float2 xd = *(const float2*)(x1 + 2 * ti + 8);
    unsigned Ah[4], Al[4];
    splitpair(xa.x * scale, xa.y * scale, Ah[0], Al[0]);
    splitpair(xb.x * scale, xb.y * scale, Ah[1], Al[1]);
    splitpair(xc.x * scale, xc.y * scale, Ah[2], Al[2]);
    splitpair(xd.x * scale, xd.y * scale, Ah[3], Al[3]);

    // Online-softmax state: running row maxes (log2 domain), D accumulators.
    float M0 = -1e30f, M1 = -1e30f;
    float D0[4] = {0, 0, 0, 0}, D1[4] = {0, 0, 0, 0};

    const uint4* b1base = s1 + g * 4 + ti;           // + cw*4
    const uint4* b2base = s2 + g * 68 + ti;          // + m*4

#pragma unroll 1
    for (int c = 0; c < 4; c++) {
        // ---- GEMM1 chunk: raw log2-logits C[8][4], codewords 64c..64c+63 ----
        float C[8][4];
#pragma unroll
        for (int j = 0; j < 8; j++) {
            uint4 B = b1base[(c * 64 + 8 * j) * 4];
            mma16816z(C[j], Ah, B.x, B.y);   // hi*hi (zero-init)
            mma16816 (C[j], Ah, B.z, B.w);   // hi*lo
            mma16816 (C[j], Al, B.x, B.y);   // lo*hi
        }
        // ---- online max update + accumulator rescale ----
        float mg = fmaxf(C[0][0], C[0][1]);
        float mh = fmaxf(C[0][2], C[0][3]);
#pragma unroll
        for (int j = 1; j < 8; j++) {
            mg = fmaxf(mg, fmaxf(C[j][0], C[j][1]));
            mh = fmaxf(mh, fmaxf(C[j][2], C[j][3]));
        }
        mg = fmaxf(mg, __shfl_xor_sync(0xffffffffu, mg, 1));
        mg = fmaxf(mg, __shfl_xor_sync(0xffffffffu, mg, 2));
        mh = fmaxf(mh, __shfl_xor_sync(0xffffffffu, mh, 1));
        mh = fmaxf(mh, __shfl_xor_sync(0xffffffffu, mh, 2));
        float Mn0 = fmaxf(M0, mg), Mn1 = fmaxf(M1, mh);
        float f0 = ex2f(M0 - Mn0);   // 0 on first chunk (M0=-1e30), D is 0
        float f1 = ex2f(M1 - Mn1);
        M0 = Mn0; M1 = Mn1;
        const float b0 = 14.f - M0, b1 = 14.f - M1;
        D0[0] *= f0; D0[1] *= f0; D1[0] *= f0; D1[1] *= f0;
        D0[2] *= f1; D0[3] *= f1; D1[2] *= f1; D1[3] *= f1;

        // ---- exp on SFU pipe + single fp16 GEMM2 accumulate ----
#pragma unroll
        for (int m = 0; m < 4; m++) {
            int mg2 = c * 4 + m;
            uint4 B2 = b2base[mg2 * 4];   // dims g (x,y) and g+8 (z,w)
            unsigned Eh[4];
            EXPH(Eh[0], C[2 * m][0],     C[2 * m][1],     b0);  // row g,   k lo
            EXPH(Eh[1], C[2 * m][2],     C[2 * m][3],     b1);  // row g+8, k lo
            EXPH(Eh[2], C[2 * m + 1][0], C[2 * m + 1][1], b0);  // row g,   k hi
            EXPH(Eh[3], C[2 * m + 1][2], C[2 * m + 1][3], b1);  // row g+8, k hi
            mma16816h(D0, Eh, B2.x, B2.y);
            mma16816h(D1, Eh, B2.z, B2.w);
        }
    }

    // ---- per-row L2 normalize over 16 dims (softmax denom + 2^(14-M) scale
    //      both cancel) ----
    float ss0 = D0[0] * D0[0] + D0[1] * D0[1] + D1[0] * D1[0] + D1[1] * D1[1];
    float ss1 = D0[2] * D0[2] + D0[3] * D0[3] + D1[2] * D1[2] + D1[3] * D1[3];
    ss0 += __shfl_xor_sync(0xffffffffu, ss0, 1);
    ss0 += __shfl_xor_sync(0xffffffffu, ss0, 2);
    ss1 += __shfl_xor_sync(0xffffffffu, ss1, 1);
    ss1 += __shfl_xor_sync(0xffffffffu, ss1, 2);
    float inv0 = rsqrtf(fmaxf(ss0, 1e-24f));
    float inv1 = rsqrtf(fmaxf(ss1, 1e-24f));

    float* o0 = out + row0 * FDIM + book * DIMS;
    float* o1 = o0 + 8 * FDIM;
    *(float2*)(o0 + 2 * ti)     = make_float2(D0[0] * inv0, D0[1] * inv0);
    *(float2*)(o0 + 2 * ti + 8) = make_float2(D1[0] * inv0, D1[1] * inv0);
    *(float2*)(o1 + 2 * ti)     = make_float2(D0[2] * inv1, D0[3] * inv1);
    *(float2*)(o1 + 2 * ti + 8) = make_float2(D1[2] * inv1, D1[3] * inv1);
}

// ---------------------------------------------------------------------------
extern "C" void kernel_launch(void* const* d_in, const int* in_sizes, int n_in,
                              void* d_out, int out_size) {
    const float* feat    = (const float*)d_in[0];
    const float* Zw      = (const float*)d_in[1];
    const float* alpha_p = (const float*)d_in[3];   // d_in[2] = n_book (unused)
    float* out = (float*)d_out;
    int N = in_sizes[0] / FDIM;

    prep_z_kernel<<<NBOOK, KCW>>>(Zw);
    soft_kernel<<<dim3(N / 128, NBOOK), 256>>>(feat, alpha_p, out);
}